// round 3
// baseline (speedup 1.0000x reference)
#include <cuda_runtime.h>

// out is a single float. Harness poisons it, so zero it first.
__global__ void mtnll_zero_kernel(float* __restrict__ out) {
    if (threadIdx.x == 0 && blockIdx.x == 0) out[0] = 0.0f;
}

__global__ __launch_bounds__(256, 8)
void mtnll_main_kernel(const float* __restrict__ in0,
                       const float* __restrict__ in1,
                       const float* __restrict__ in2,
                       const float* __restrict__ cmap,
                       const int* __restrict__ t0,   // jax int64 -> int32 (x64 disabled)
                       const int* __restrict__ t1,
                       const int* __restrict__ t2,
                       float* __restrict__ out,
                       int n) {
    const float inv_n = 1.0f / (float)n;
    float acc = 0.0f;

    const int stride = gridDim.x * blockDim.x;
    for (int i = blockIdx.x * blockDim.x + threadIdx.x; i < n; i += stride) {
        // 7 independent load streams -> high MLP, all coalesced or near-coalesced
        const int a = __ldg(&t0[i]);
        const int b = __ldg(&t1[i]);
        const int c = __ldg(&t2[i]);
        const float w  = __ldg(&cmap[i]);
        const float p0 = __ldg(&in0[3 * i + a]);
        const float p1 = __ldg(&in1[3 * i + b]);
        const float p2 = __ldg(&in2[3 * i + c]);
        // weighted sum: 1.0*p0 + 0.5*p1 + 0.25*p2, then * (-w)
        const float s = fmaf(0.5f, p1, fmaf(0.25f, p2, p0));
        acc = fmaf(-w, s, acc);
    }

    // warp reduction
    #pragma unroll
    for (int o = 16; o > 0; o >>= 1)
        acc += __shfl_xor_sync(0xffffffffu, acc, o);

    __shared__ float smem[8];
    const int warp = threadIdx.x >> 5;
    const int lane = threadIdx.x & 31;
    if (lane == 0) smem[warp] = acc;
    __syncthreads();

    if (warp == 0) {
        acc = (lane < 8) ? smem[lane] : 0.0f;
        #pragma unroll
        for (int o = 4; o > 0; o >>= 1)
            acc += __shfl_xor_sync(0xffffffffu, acc, o);
        if (lane == 0)
            atomicAdd(out, acc * inv_n);
    }
}

extern "C" void kernel_launch(void* const* d_in, const int* in_sizes, int n_in,
                              void* d_out, int out_size) {
    const float* in0      = (const float*)d_in[0];
    const float* in1      = (const float*)d_in[1];
    const float* in2      = (const float*)d_in[2];
    const float* cmap     = (const float*)d_in[3];
    const int* t0         = (const int*)d_in[4];
    const int* t1         = (const int*)d_in[5];
    const int* t2         = (const int*)d_in[6];
    float* out = (float*)d_out;

    const int n = in_sizes[3];  // cmap element count == N

    mtnll_zero_kernel<<<1, 32>>>(out);

    const int block = 256;
    int grid = (n + block * 8 - 1) / (block * 8);  // ~8 rows per thread
    if (grid < 1) grid = 1;
    if (grid > 4096) grid = 4096;
    mtnll_main_kernel<<<grid, block>>>(in0, in1, in2, cmap, t0, t1, t2, out, n);
}